// round 1
// baseline (speedup 1.0000x reference)
#include <cuda_runtime.h>
#include <math.h>

// Problem dims (fixed by the reference): B=16, S=1024, H=1024, K=256
#define BATCH 16
#define SEQ   1024
#define HID   1024
#define KIDX  256
#define MTOT  (BATCH * KIDX)   // 4096 output rows per span

// Tiling
#define BM   64
#define BN   64
#define BKC  16
#define SROW 68                // BM + 4 pad (keeps float4 alignment, dodges conflicts)

__device__ int g_is64[2];

// prem_word_idxs may be int64 (values < 1024 -> high 32-bit words all zero).
// hypo_word_idxs is always int32. Detect once, no host sync.
__global__ void detect_idx_kernel(const unsigned int* __restrict__ prem_raw) {
    if (threadIdx.x == 0) {
        int all_zero = 1;
        #pragma unroll
        for (int i = 0; i < 32; i++) {
            if (prem_raw[2 * i + 1] != 0u) all_zero = 0;
        }
        g_is64[0] = all_zero;  // prem
        g_is64[1] = 0;         // hypo: always int32
    }
}

// Fused gather + 5-way GEMM + combine + tanh for one span.
// out[m, o] = tanh( Xs@W1^T + Xe@W2^T + (Xs-Xe)@W3^T + (b1+b2)
//                   + (Xs@W4^T + b4) * (Xe@W4^T + b4) )
__global__ __launch_bounds__(256, 2)
void span_kernel(const float* __restrict__ x,
                 const void*  __restrict__ idx_raw,
                 int flag_idx,
                 const float* __restrict__ W1, const float* __restrict__ b1,
                 const float* __restrict__ W2, const float* __restrict__ b2,
                 const float* __restrict__ W3,
                 const float* __restrict__ W4, const float* __restrict__ b4,
                 float* __restrict__ out)
{
    __shared__ float As[BKC][SROW];
    __shared__ float Ae[BKC][SROW];
    __shared__ float Wsm[4][BKC][SROW];

    const int tid = threadIdx.x;
    const int m0  = blockIdx.y * BM;
    const int n0  = blockIdx.x * BN;

    // loader role: 64 rows x 16 k-cols, one float4 per thread per array
    const int lrow = tid >> 2;          // 0..63
    const int lk   = (tid & 3) << 2;    // 0,4,8,12

    // Resolve this thread's gathered A-row pointers once.
    const int mrow = m0 + lrow;
    const int bb   = mrow >> 8;          // / KIDX
    const int kk_  = mrow & (KIDX - 1);
    int s_idx, e_idx;
    if (g_is64[flag_idx]) {
        const long long* idx = (const long long*)idx_raw;
        s_idx = (int)idx[(size_t)bb * 2 * KIDX + kk_];
        e_idx = (int)idx[(size_t)bb * 2 * KIDX + KIDX + kk_];
    } else {
        const int* idx = (const int*)idx_raw;
        s_idx = idx[bb * 2 * KIDX + kk_];
        e_idx = idx[bb * 2 * KIDX + KIDX + kk_];
    }
    const float* xs  = x  + ((size_t)bb * SEQ + s_idx) * HID + lk;
    const float* xe  = x  + ((size_t)bb * SEQ + e_idx) * HID + lk;
    const float* w1p = W1 + (size_t)(n0 + lrow) * HID + lk;
    const float* w2p = W2 + (size_t)(n0 + lrow) * HID + lk;
    const float* w3p = W3 + (size_t)(n0 + lrow) * HID + lk;
    const float* w4p = W4 + (size_t)(n0 + lrow) * HID + lk;

    // compute role: 4x4 thread tile
    const int tm = (tid >> 4) << 2;     // m offset within block
    const int tn = (tid & 15) << 2;     // n offset within block

    float accL [4][4] = {};
    float acc4s[4][4] = {};
    float acc4e[4][4] = {};

    for (int kt = 0; kt < HID; kt += BKC) {
        float4 vs = *(const float4*)(xs  + kt);
        float4 ve = *(const float4*)(xe  + kt);
        float4 v1 = *(const float4*)(w1p + kt);
        float4 v2 = *(const float4*)(w2p + kt);
        float4 v3 = *(const float4*)(w3p + kt);
        float4 v4 = *(const float4*)(w4p + kt);

        As[lk+0][lrow] = vs.x; As[lk+1][lrow] = vs.y;
        As[lk+2][lrow] = vs.z; As[lk+3][lrow] = vs.w;
        Ae[lk+0][lrow] = ve.x; Ae[lk+1][lrow] = ve.y;
        Ae[lk+2][lrow] = ve.z; Ae[lk+3][lrow] = ve.w;
        Wsm[0][lk+0][lrow] = v1.x; Wsm[0][lk+1][lrow] = v1.y;
        Wsm[0][lk+2][lrow] = v1.z; Wsm[0][lk+3][lrow] = v1.w;
        Wsm[1][lk+0][lrow] = v2.x; Wsm[1][lk+1][lrow] = v2.y;
        Wsm[1][lk+2][lrow] = v2.z; Wsm[1][lk+3][lrow] = v2.w;
        Wsm[2][lk+0][lrow] = v3.x; Wsm[2][lk+1][lrow] = v3.y;
        Wsm[2][lk+2][lrow] = v3.z; Wsm[2][lk+3][lrow] = v3.w;
        Wsm[3][lk+0][lrow] = v4.x; Wsm[3][lk+1][lrow] = v4.y;
        Wsm[3][lk+2][lrow] = v4.z; Wsm[3][lk+3][lrow] = v4.w;

        __syncthreads();

        #pragma unroll
        for (int kk = 0; kk < BKC; kk++) {
            float4 a_s4 = *(const float4*)&As[kk][tm];
            float4 a_e4 = *(const float4*)&Ae[kk][tm];
            float4 w1v  = *(const float4*)&Wsm[0][kk][tn];
            float4 w2v  = *(const float4*)&Wsm[1][kk][tn];
            float4 w3v  = *(const float4*)&Wsm[2][kk][tn];
            float4 w4v  = *(const float4*)&Wsm[3][kk][tn];

            float as_[4] = {a_s4.x, a_s4.y, a_s4.z, a_s4.w};
            float ae_[4] = {a_e4.x, a_e4.y, a_e4.z, a_e4.w};
            float w1a[4] = {w1v.x, w1v.y, w1v.z, w1v.w};
            float w2a[4] = {w2v.x, w2v.y, w2v.z, w2v.w};
            float w3a[4] = {w3v.x, w3v.y, w3v.z, w3v.w};
            float w4a[4] = {w4v.x, w4v.y, w4v.z, w4v.w};
            float ad_[4];
            #pragma unroll
            for (int i = 0; i < 4; i++) ad_[i] = as_[i] - ae_[i];

            #pragma unroll
            for (int i = 0; i < 4; i++) {
                #pragma unroll
                for (int j = 0; j < 4; j++) {
                    accL [i][j] = fmaf(as_[i], w1a[j], accL [i][j]);
                    accL [i][j] = fmaf(ae_[i], w2a[j], accL [i][j]);
                    accL [i][j] = fmaf(ad_[i], w3a[j], accL [i][j]);
                    acc4s[i][j] = fmaf(as_[i], w4a[j], acc4s[i][j]);
                    acc4e[i][j] = fmaf(ae_[i], w4a[j], acc4e[i][j]);
                }
            }
        }
        __syncthreads();
    }

    // Epilogue: combine, tanh, store (float4 per m-row)
    float res[4][4];
    #pragma unroll
    for (int j = 0; j < 4; j++) {
        const int o   = n0 + tn + j;
        const float c12 = b1[o] + b2[o];
        const float bb4 = b4[o];
        #pragma unroll
        for (int i = 0; i < 4; i++) {
            float v = accL[i][j] + c12 + (acc4s[i][j] + bb4) * (acc4e[i][j] + bb4);
            res[i][j] = tanhf(v);
        }
    }
    #pragma unroll
    for (int i = 0; i < 4; i++) {
        const int m = m0 + tm + i;
        float4 o4 = make_float4(res[i][0], res[i][1], res[i][2], res[i][3]);
        *(float4*)&out[(size_t)m * HID + n0 + tn] = o4;
    }
}

extern "C" void kernel_launch(void* const* d_in, const int* in_sizes, int n_in,
                              void* d_out, int out_size) {
    const float* x        = (const float*)d_in[0];
    const void*  prem_idx = d_in[1];
    const void*  hypo_idx = d_in[2];
    const float* Wp1 = (const float*)d_in[3];
    const float* bp1 = (const float*)d_in[4];
    const float* Wp2 = (const float*)d_in[5];
    const float* bp2 = (const float*)d_in[6];
    const float* Wp3 = (const float*)d_in[7];
    // d_in[8] = bp3 (cancels in the math)
    const float* Wp4 = (const float*)d_in[9];
    const float* bp4 = (const float*)d_in[10];
    const float* Wh1 = (const float*)d_in[11];
    const float* bh1 = (const float*)d_in[12];
    const float* Wh2 = (const float*)d_in[13];
    const float* bh2 = (const float*)d_in[14];
    const float* Wh3 = (const float*)d_in[15];
    // d_in[16] = bh3 (cancels)
    const float* Wh4 = (const float*)d_in[17];
    const float* bh4 = (const float*)d_in[18];

    float* out = (float*)d_out;

    detect_idx_kernel<<<1, 32>>>((const unsigned int*)prem_idx);

    dim3 grid(HID / BN, MTOT / BM);
    span_kernel<<<grid, 256>>>(x, prem_idx, 0,
                               Wp1, bp1, Wp2, bp2, Wp3, Wp4, bp4,
                               out);
    span_kernel<<<grid, 256>>>(x, hypo_idx, 1,
                               Wh1, bh1, Wh2, bh2, Wh3, Wh4, bh4,
                               out + (size_t)MTOT * HID);
}

// round 4
// speedup vs baseline: 5.3773x; 5.3773x over previous
#include <cuda_runtime.h>
#include <math.h>
#include <stdint.h>

// Problem dims: B=16, S=1024, H=1024, K=256
#define BATCH 16
#define SEQ   1024
#define HID   1024
#define KIDX  256
#define MTOT  (BATCH * KIDX)      // 4096 rows per span

// GEMM tiling: CTA 64x128, 8 warps (2x4), warp tile 32x32, k-chunk 16
#define TM    64
#define TN    128
#define KC    16
#define ROWP  20                   // padded row stride in floats (16 data + 4 pad)
#define A_FL  (64 * ROWP)          // 1280 floats per A operand tile
#define B_FL  (128 * ROWP)         // 2560 floats per B operand tile
#define STAGE_FL (2 * A_FL + 3 * B_FL)   // 10240 floats = 40KB
#define NCH   (HID / KC)           // 64 chunks
#define SMEM_BYTES (2 * STAGE_FL * 4)    // 80KB

// ---------------- device scratch (static: allocation-free) ----------------
__device__ float g_A[2][2][(size_t)MTOT * HID];   // gathered rows (tf32-rounded)
__device__ float g_W13[2][(size_t)HID * HID];     // W1+W3 (tf32-rounded)
__device__ float g_W23[2][(size_t)HID * HID];     // W2-W3 (tf32-rounded)
__device__ float g_W4r[2][(size_t)HID * HID];     // W4 (tf32-rounded)
__device__ float g_c12[2][HID];                   // b1+b2 (full fp32)
__device__ int   g_is64[2];

// ---------------- helpers ----------------
__device__ __forceinline__ uint32_t smem_u32(const void* p) {
    uint32_t a;
    asm("{ .reg .u64 t; cvta.to.shared.u64 t, %1; cvt.u32.u64 %0, t; }" : "=r"(a) : "l"(p));
    return a;
}
__device__ __forceinline__ float tf32r(float f) {
    uint32_t u;
    asm("cvt.rna.tf32.f32 %0, %1;" : "=r"(u) : "f"(f));
    return __uint_as_float(u);
}

#define MMA_TF32(c, a, b0_, b1_) \
    asm volatile("mma.sync.aligned.m16n8k8.row.col.f32.tf32.tf32.f32 " \
        "{%0,%1,%2,%3}, {%4,%5,%6,%7}, {%8,%9}, {%0,%1,%2,%3};" \
        : "+f"((c)[0]), "+f"((c)[1]), "+f"((c)[2]), "+f"((c)[3]) \
        : "r"((a)[0]), "r"((a)[1]), "r"((a)[2]), "r"((a)[3]), "r"(b0_), "r"(b1_))

// ---------------- prep kernels ----------------
__global__ void detect_idx_kernel(const unsigned int* __restrict__ prem_raw) {
    if (threadIdx.x == 0) {
        int all_zero = 1;
        #pragma unroll
        for (int i = 0; i < 32; i++)
            if (prem_raw[2 * i + 1] != 0u) all_zero = 0;
        g_is64[0] = all_zero;
        g_is64[1] = 0;
    }
}

__global__ void prep_weights(const float4* __restrict__ Wp1, const float4* __restrict__ Wp2,
                             const float4* __restrict__ Wp3, const float4* __restrict__ Wp4,
                             const float4* __restrict__ Wh1, const float4* __restrict__ Wh2,
                             const float4* __restrict__ Wh3, const float4* __restrict__ Wh4,
                             const float* __restrict__ bp1, const float* __restrict__ bp2,
                             const float* __restrict__ bh1, const float* __restrict__ bh2) {
    int i = blockIdx.x * blockDim.x + threadIdx.x;  // 0 .. H*H/4-1
    float4 a = Wp1[i], b = Wp2[i], c = Wp3[i], d = Wp4[i];
    ((float4*)g_W13[0])[i] = make_float4(tf32r(a.x + c.x), tf32r(a.y + c.y),
                                         tf32r(a.z + c.z), tf32r(a.w + c.w));
    ((float4*)g_W23[0])[i] = make_float4(tf32r(b.x - c.x), tf32r(b.y - c.y),
                                         tf32r(b.z - c.z), tf32r(b.w - c.w));
    ((float4*)g_W4r[0])[i] = make_float4(tf32r(d.x), tf32r(d.y), tf32r(d.z), tf32r(d.w));
    a = Wh1[i]; b = Wh2[i]; c = Wh3[i]; d = Wh4[i];
    ((float4*)g_W13[1])[i] = make_float4(tf32r(a.x + c.x), tf32r(a.y + c.y),
                                         tf32r(a.z + c.z), tf32r(a.w + c.w));
    ((float4*)g_W23[1])[i] = make_float4(tf32r(b.x - c.x), tf32r(b.y - c.y),
                                         tf32r(b.z - c.z), tf32r(b.w - c.w));
    ((float4*)g_W4r[1])[i] = make_float4(tf32r(d.x), tf32r(d.y), tf32r(d.z), tf32r(d.w));
    if (i < HID) {
        g_c12[0][i] = bp1[i] + bp2[i];
        g_c12[1][i] = bh1[i] + bh2[i];
    }
}

// grid (MTOT, 2 which, 2 span), 256 threads: copy+round one gathered row (4KB)
__global__ void gather_kernel(const float* __restrict__ x,
                              const void* __restrict__ prem,
                              const void* __restrict__ hypo) {
    const int m = blockIdx.x;
    const int which = blockIdx.y;
    const int span = blockIdx.z;
    const void* idx_raw = span ? hypo : prem;
    const int b = m >> 8;
    const int k = m & (KIDX - 1);
    const long off = ((long)b * 2 + which) * KIDX + k;
    int s;
    if (g_is64[span]) s = (int)((const long long*)idx_raw)[off];
    else              s = ((const int*)idx_raw)[off];
    const float4* src = (const float4*)(x + ((size_t)b * SEQ + s) * HID);
    float4 v = src[threadIdx.x];
    float4* dst = (float4*)(g_A[span][which] + (size_t)m * HID);
    dst[threadIdx.x] = make_float4(tf32r(v.x), tf32r(v.y), tf32r(v.z), tf32r(v.w));
}

// ---------------- main fused GEMM (tf32 mma.sync) ----------------
// out = tanh(accL + c12 + (acc4s+b4)*(acc4e+b4))
//   accL  = Xs@W13^T + Xe@W23^T
//   acc4s = Xs@W4^T ; acc4e = Xe@W4^T
__global__ __launch_bounds__(256, 1)
void gemm_kernel(const float* __restrict__ bp4, const float* __restrict__ bh4,
                 float* __restrict__ out) {
    extern __shared__ float smf[];
    const int tid  = threadIdx.x;
    const int wid  = tid >> 5;
    const int lane = tid & 31;
    const int span = blockIdx.z;
    const int n0   = blockIdx.x * TN;
    const int m0   = blockIdx.y * TM;
    const int wm   = wid >> 2;      // 0..1
    const int wn   = wid & 3;       // 0..3

    // loader slots: 2048 float4 per chunk / 256 threads = 8 slots
    const float* gp[8];
    int so[8];
    #pragma unroll
    for (int s = 0; s < 8; s++) {
        const int vid = s * 256 + tid;
        if (vid < 512) {                       // A operands: As, Ae (64 rows x 4 quads)
            const int a = vid >> 8;
            const int r = (vid & 255) >> 2;
            const int q = vid & 3;
            gp[s] = g_A[span][a] + (size_t)(m0 + r) * HID + q * 4;
            so[s] = a * A_FL + r * ROWP + q * 4;
        } else {                               // B operands: W13, W23, W4 (128 rows x 4 quads)
            const int w  = vid - 512;
            const int op = w >> 9;
            const int r  = (w & 511) >> 2;
            const int q  = w & 3;
            const float* wb = (op == 0) ? g_W13[span] : (op == 1 ? g_W23[span] : g_W4r[span]);
            gp[s] = wb + (size_t)(n0 + r) * HID + q * 4;
            so[s] = 2 * A_FL + op * B_FL + r * ROWP + q * 4;
        }
    }
    const uint32_t sbu = smem_u32(smf);

    // fragment base offsets (floats)
    const int aB = (wm * 32 + (lane >> 2)) * ROWP + (lane & 3);
    const int bB = (wn * 32 + (lane >> 2)) * ROWP + (lane & 3);

    float accL[2][4][4] = {}, ac4s[2][4][4] = {}, ac4e[2][4][4] = {};

#define LOAD_CHUNK(ch, st) do {                                                   \
        const int _k = (ch) * KC;                                                 \
        _Pragma("unroll")                                                         \
        for (int _s = 0; _s < 8; _s++) {                                          \
            uint32_t _d = sbu + (uint32_t)(((st) * STAGE_FL + so[_s]) * 4);       \
            asm volatile("cp.async.cg.shared.global [%0], [%1], 16;"              \
                         :: "r"(_d), "l"(gp[_s] + _k) : "memory");                \
        }                                                                         \
        asm volatile("cp.async.commit_group;" ::: "memory");                      \
    } while (0)

    LOAD_CHUNK(0, 0);

    for (int ch = 0; ch < NCH; ch++) {
        const int cur = ch & 1;
        if (ch + 1 < NCH) {
            LOAD_CHUNK(ch + 1, cur ^ 1);
            asm volatile("cp.async.wait_group 1;" ::: "memory");
        } else {
            asm volatile("cp.async.wait_group 0;" ::: "memory");
        }
        __syncthreads();

        const int S0 = cur * STAGE_FL;
        #pragma unroll
        for (int kb = 0; kb < KC; kb += 8) {
            // A fragments: af[As/Ae][mt][4]
            uint32_t af[2][2][4];
            #pragma unroll
            for (int mt = 0; mt < 2; mt++) {
                const int b0 = S0 + aB + mt * 16 * ROWP + kb;
                af[0][mt][0] = __float_as_uint(smf[b0]);
                af[0][mt][1] = __float_as_uint(smf[b0 + 8 * ROWP]);
                af[0][mt][2] = __float_as_uint(smf[b0 + 4]);
                af[0][mt][3] = __float_as_uint(smf[b0 + 8 * ROWP + 4]);
                const int b1 = b0 + A_FL;
                af[1][mt][0] = __float_as_uint(smf[b1]);
                af[1][mt][1] = __float_as_uint(smf[b1 + 8 * ROWP]);
                af[1][mt][2] = __float_as_uint(smf[b1 + 4]);
                af[1][mt][3] = __float_as_uint(smf[b1 + 8 * ROWP + 4]);
            }
            #pragma unroll
            for (int nt = 0; nt < 4; nt++) {
                const int bb = S0 + 2 * A_FL + bB + nt * 8 * ROWP + kb;
                const uint32_t w13a = __float_as_uint(smf[bb]);
                const uint32_t w13b = __float_as_uint(smf[bb + 4]);
                const uint32_t w23a = __float_as_uint(smf[bb + B_FL]);
                const uint32_t w23b = __float_as_uint(smf[bb + B_FL + 4]);
                const uint32_t w4a  = __float_as_uint(smf[bb + 2 * B_FL]);
                const uint32_t w4b  = __float_as_uint(smf[bb + 2 * B_FL + 4]);
                #pragma unroll
                for (int mt = 0; mt < 2; mt++) {
                    MMA_TF32(accL[mt][nt], af[0][mt], w13a, w13b);
                    MMA_TF32(accL[mt][nt], af[1][mt], w23a, w23b);
                    MMA_TF32(ac4s[mt][nt], af[0][mt], w4a, w4b);
                    MMA_TF32(ac4e[mt][nt], af[1][mt], w4a, w4b);
                }
            }
        }
        __syncthreads();
    }

    // epilogue
    const float* b4p  = span ? bh4 : bp4;
    const float* c12p = g_c12[span];
    float* outp = out + (size_t)span * MTOT * HID;

    #pragma unroll
    for (int mt = 0; mt < 2; mt++) {
        const int r0 = m0 + wm * 32 + mt * 16 + (lane >> 2);
        #pragma unroll
        for (int nt = 0; nt < 4; nt++) {
            const int o = n0 + wn * 32 + nt * 8 + (lane & 3) * 2;
            const float c0 = c12p[o],   c1 = c12p[o + 1];
            const float d0 = b4p[o],    d1 = b4p[o + 1];
            float v0 = accL[mt][nt][0] + c0 + (ac4s[mt][nt][0] + d0) * (ac4e[mt][nt][0] + d0);
            float v1 = accL[mt][nt][1] + c1 + (ac4s[mt][nt][1] + d1) * (ac4e[mt][nt][1] + d1);
            *(float2*)&outp[(size_t)r0 * HID + o] = make_float2(tanhf(v0), tanhf(v1));
            float v2 = accL[mt][nt][2] + c0 + (ac4s[mt][nt][2] + d0) * (ac4e[mt][nt][2] + d0);
            float v3 = accL[mt][nt][3] + c1 + (ac4s[mt][nt][3] + d1) * (ac4e[mt][nt][3] + d1);
            *(float2*)&outp[(size_t)(r0 + 8) * HID + o] = make_float2(tanhf(v2), tanhf(v3));
        }
    }
}

// ---------------- launch ----------------
extern "C" void kernel_launch(void* const* d_in, const int* in_sizes, int n_in,
                              void* d_out, int out_size) {
    const float* x    = (const float*)d_in[0];
    const void*  prem = d_in[1];
    const void*  hypo = d_in[2];
    const float* Wp1 = (const float*)d_in[3];
    const float* bp1 = (const float*)d_in[4];
    const float* Wp2 = (const float*)d_in[5];
    const float* bp2 = (const float*)d_in[6];
    const float* Wp3 = (const float*)d_in[7];
    const float* Wp4 = (const float*)d_in[9];
    const float* bp4 = (const float*)d_in[10];
    const float* Wh1 = (const float*)d_in[11];
    const float* bh1 = (const float*)d_in[12];
    const float* Wh2 = (const float*)d_in[13];
    const float* bh2 = (const float*)d_in[14];
    const float* Wh3 = (const float*)d_in[15];
    const float* Wh4 = (const float*)d_in[17];
    const float* bh4 = (const float*)d_in[18];
    float* out = (float*)d_out;

    detect_idx_kernel<<<1, 32>>>((const unsigned int*)prem);

    prep_weights<<<512, 512>>>((const float4*)Wp1, (const float4*)Wp2,
                               (const float4*)Wp3, (const float4*)Wp4,
                               (const float4*)Wh1, (const float4*)Wh2,
                               (const float4*)Wh3, (const float4*)Wh4,
                               bp1, bp2, bh1, bh2);

    gather_kernel<<<dim3(MTOT, 2, 2), 256>>>(x, prem, hypo);

    cudaFuncSetAttribute(gemm_kernel, cudaFuncAttributeMaxDynamicSharedMemorySize, SMEM_BYTES);
    gemm_kernel<<<dim3(HID / TN, MTOT / TM, 2), 256, SMEM_BYTES>>>(bp4, bh4, out);
}

// round 6
// speedup vs baseline: 7.1231x; 1.3247x over previous
#include <cuda_runtime.h>
#include <math.h>
#include <stdint.h>

// Problem dims: B=16, S=1024, H=1024, K=256
#define BATCH 16
#define SEQ   1024
#define HID   1024
#define KIDX  256
#define MTOT  (BATCH * KIDX)      // 4096 rows per span
#define MBT   (MTOT / 16)          // 256 m-blocks (16 rows each)
#define NBT   (HID / 8)            // 128 n-blocks (8 cols each)
#define KB8T  (HID / 8)            // 128 k-blocks (8 k each)

// GEMM tiling: CTA 64x128, 8 warps (2x4), warp tile 32x32, k-chunk 16 (2 kb8)
#define TM    64
#define TN    128
#define NCH   (HID / 16)           // 64 chunks
#define STAGES 4
#define STAGE_FL 8192              // floats per stage: A 2048 + B 6144 (32KB)
#define SMEM_BYTES (STAGES * STAGE_FL * 4)   // 128KB

// ---------------- device scratch (fragment-ordered, tf32-rounded) -------
// A: [span][which][mb][kb8][lane] float4 = {A[r][c],A[r+8][c],A[r][c+4],A[r+8][c+4]},
//    r=lane>>2, c=lane&3 (within 16x8 block). 16MB each.
__device__ float g_Af[2][2][(size_t)MBT * KB8T * 32 * 4];
// B: [span][op][nb][kb8][lane] float2 = {W[n][k],W[n][k+4]}, n=lane>>2,k=lane&3. op: W13,W23,W4
__device__ float g_Wf[2][3][(size_t)NBT * KB8T * 32 * 2];
__device__ float g_c12[2][HID];
__device__ int   g_is64[2];

// ---------------- helpers ----------------
__device__ __forceinline__ uint32_t smem_u32(const void* p) {
    uint32_t a;
    asm("{ .reg .u64 t; cvta.to.shared.u64 t, %1; cvt.u32.u64 %0, t; }" : "=r"(a) : "l"(p));
    return a;
}
__device__ __forceinline__ float tf32r(float f) {
    uint32_t u;
    asm("cvt.rna.tf32.f32 %0, %1;" : "=r"(u) : "f"(f));
    return __uint_as_float(u);
}

#define MMA_TF32(c, a, b_) \
    asm volatile("mma.sync.aligned.m16n8k8.row.col.f32.tf32.tf32.f32 " \
        "{%0,%1,%2,%3}, {%4,%5,%6,%7}, {%8,%9}, {%0,%1,%2,%3};" \
        : "+f"((c)[0]), "+f"((c)[1]), "+f"((c)[2]), "+f"((c)[3]) \
        : "r"(__float_as_uint((a).x)), "r"(__float_as_uint((a).y)), \
          "r"(__float_as_uint((a).z)), "r"(__float_as_uint((a).w)), \
          "r"(__float_as_uint((b_).x)), "r"(__float_as_uint((b_).y)))

// ---------------- prep kernels ----------------
__global__ void detect_idx_kernel(const unsigned int* __restrict__ prem_raw) {
    if (threadIdx.x == 0) {
        int all_zero = 1;
        #pragma unroll
        for (int i = 0; i < 32; i++)
            if (prem_raw[2 * i + 1] != 0u) all_zero = 0;
        g_is64[0] = all_zero;
        g_is64[1] = 0;
    }
}

__global__ void bias_kernel(const float* __restrict__ bp1, const float* __restrict__ bp2,
                            const float* __restrict__ bh1, const float* __restrict__ bh2) {
    int i = threadIdx.x;
    g_c12[0][i] = bp1[i] + bp2[i];
    g_c12[1][i] = bh1[i] + bh2[i];
}

// grid (MBT, 2 which, 2 span), 256 threads: gather 16 rows -> fragment layout
__global__ void gather_permute(const float* __restrict__ x,
                               const void* __restrict__ prem,
                               const void* __restrict__ hypo) {
    const int mb    = blockIdx.x;
    const int which = blockIdx.y;
    const int span  = blockIdx.z;
    const void* idx_raw = span ? hypo : prem;

    __shared__ int sidx[16];
    if (threadIdx.x < 16) {
        const int m = mb * 16 + threadIdx.x;
        const int b = m >> 8;
        const int k = m & (KIDX - 1);
        const long off = ((long)b * 2 + which) * KIDX + k;
        int s;
        if (g_is64[span]) s = (int)((const long long*)idx_raw)[off];
        else              s = ((const int*)idx_raw)[off];
        sidx[threadIdx.x] = b * SEQ + s;
    }
    __syncthreads();

    const int lane = threadIdx.x & 31;
    const int w    = threadIdx.x >> 5;
    const int r    = lane >> 2;
    const int c    = lane & 3;
    const float* r0p = x + (size_t)sidx[r] * HID;
    const float* r8p = x + (size_t)sidx[r + 8] * HID;
    float4* dst = (float4*)g_Af[span][which] + (size_t)mb * KB8T * 32;

    #pragma unroll
    for (int i = 0; i < 16; i++) {
        const int kb8 = w + 8 * i;
        const int k = kb8 * 8 + c;
        float4 v = make_float4(tf32r(__ldg(r0p + k)),     tf32r(__ldg(r8p + k)),
                               tf32r(__ldg(r0p + k + 4)), tf32r(__ldg(r8p + k + 4)));
        dst[(size_t)kb8 * 32 + lane] = v;
    }
}

// grid (NBT, 2 span), 256 threads: fold weights -> fragment layout
__global__ void weights_permute(const float* __restrict__ Wp1, const float* __restrict__ Wp2,
                                const float* __restrict__ Wp3, const float* __restrict__ Wp4,
                                const float* __restrict__ Wh1, const float* __restrict__ Wh2,
                                const float* __restrict__ Wh3, const float* __restrict__ Wh4) {
    const int nb   = blockIdx.x;
    const int span = blockIdx.y;
    const float* W1 = span ? Wh1 : Wp1;
    const float* W2 = span ? Wh2 : Wp2;
    const float* W3 = span ? Wh3 : Wp3;
    const float* W4 = span ? Wh4 : Wp4;

    const int lane = threadIdx.x & 31;
    const int w    = threadIdx.x >> 5;
    const int n    = nb * 8 + (lane >> 2);
    const int c    = lane & 3;
    float2* d13 = (float2*)g_Wf[span][0] + (size_t)nb * KB8T * 32;
    float2* d23 = (float2*)g_Wf[span][1] + (size_t)nb * KB8T * 32;
    float2* d4  = (float2*)g_Wf[span][2] + (size_t)nb * KB8T * 32;

    #pragma unroll
    for (int i = 0; i < 16; i++) {
        const int kb8 = w + 8 * i;
        const size_t ka = (size_t)n * HID + kb8 * 8 + c;
        const float w1a = __ldg(W1 + ka), w1b = __ldg(W1 + ka + 4);
        const float w2a = __ldg(W2 + ka), w2b = __ldg(W2 + ka + 4);
        const float w3a = __ldg(W3 + ka), w3b = __ldg(W3 + ka + 4);
        const float w4a = __ldg(W4 + ka), w4b = __ldg(W4 + ka + 4);
        const size_t o = (size_t)kb8 * 32 + lane;
        d13[o] = make_float2(tf32r(w1a + w3a), tf32r(w1b + w3b));
        d23[o] = make_float2(tf32r(w2a - w3a), tf32r(w2b - w3b));
        d4[o]  = make_float2(tf32r(w4a), tf32r(w4b));
    }
}

// ---------------- main fused GEMM (tf32 mma.sync, fragment smem) ---------
// out = tanh(accL + c12 + (ac4s+b4)*(ac4e+b4))
__global__ __launch_bounds__(256, 1)
void gemm_kernel(const float* __restrict__ bp4, const float* __restrict__ bh4,
                 float* __restrict__ out) {
    extern __shared__ float smf[];
    const int tid  = threadIdx.x;
    const int wid  = tid >> 5;
    const int lane = tid & 31;
    const int span = blockIdx.z;
    const int n0   = blockIdx.x * TN;
    const int m0   = blockIdx.y * TM;
    const int mb0  = m0 >> 4;          // first m-block
    const int nb0  = n0 >> 3;          // first n-block
    const int wm   = wid >> 2;         // 0..1
    const int wn   = wid & 3;          // 0..3

    // loader slots: 2048 x 16B per chunk / 256 threads = 8 slots.
    // smem stage layout (floats): A [0, 2048), B [2048, 8192)
    // slots 0,1 -> A (v = s*256+tid < 512); slots 2..7 -> B (u = v-512)
    const float4* gb[8];
    int so[8], adv[8];
    #pragma unroll
    for (int s = 0; s < 8; s++) {
        const int v = s * 256 + tid;
        if (v < 512) {
            const int o   = v >> 8;
            const int mbl = (v >> 6) & 3;
            gb[s]  = (const float4*)g_Af[span][o] +
                     (size_t)(mb0 + mbl) * (KB8T * 32) + (v & 63);
            so[s]  = v * 4;                 // float offset within stage
            adv[s] = 64;
        } else {
            const int u  = v - 512;
            const int w  = u >> 9;
            const int nb = (u >> 5) & 15;
            gb[s]  = (const float4*)g_Wf[span][w] +
                     (size_t)(nb0 + nb) * (KB8T * 16) + (u & 31);
            so[s]  = 2048 + u * 4;          // B base = 2048 floats (FIXED)
            adv[s] = 32;
        }
    }
    const uint32_t sbu = smem_u32(smf);

#define LOAD_CHUNK(ch) do {                                                      \
        const int _st = (ch) & (STAGES - 1);                                     \
        _Pragma("unroll")                                                        \
        for (int _s = 0; _s < 8; _s++) {                                         \
            uint32_t _d = sbu + (uint32_t)((_st * STAGE_FL + so[_s]) * 4);       \
            asm volatile("cp.async.cg.shared.global [%0], [%1], 16;"             \
                         :: "r"(_d), "l"(gb[_s] + (size_t)(ch) * adv[_s])        \
                         : "memory");                                            \
        }                                                                        \
    } while (0)

    float accL[2][4][4] = {}, ac4s[2][4][4] = {}, ac4e[2][4][4] = {};

    // prologue: 3 chunks in flight
    #pragma unroll
    for (int p = 0; p < STAGES - 1; p++) {
        LOAD_CHUNK(p);
        asm volatile("cp.async.commit_group;" ::: "memory");
    }

    // precomputed fragment offsets (floats)
    const int aOff = lane * 4;         // + ((o*4+mbl)*2+kbl)*128
    const int bOff = 2048 + lane * 2;  // + ((w*16+nbl)*2+kbl)*64

    for (int ch = 0; ch < NCH; ch++) {
        asm volatile("cp.async.wait_group %0;" :: "n"(STAGES - 2) : "memory");
        __syncthreads();
        if (ch + STAGES - 1 < NCH) LOAD_CHUNK(ch + STAGES - 1);
        asm volatile("cp.async.commit_group;" ::: "memory");

        const int S0 = (ch & (STAGES - 1)) * STAGE_FL;
        #pragma unroll
        for (int kbl = 0; kbl < 2; kbl++) {
            float4 af[2][2];
            #pragma unroll
            for (int o = 0; o < 2; o++)
                #pragma unroll
                for (int mt = 0; mt < 2; mt++)
                    af[o][mt] = *(const float4*)(smf + S0 + aOff +
                                ((o * 4 + wm * 2 + mt) * 2 + kbl) * 128);
            float2 bf[3][4];
            #pragma unroll
            for (int w = 0; w < 3; w++)
                #pragma unroll
                for (int nt = 0; nt < 4; nt++)
                    bf[w][nt] = *(const float2*)(smf + S0 + bOff +
                                ((w * 16 + wn * 4 + nt) * 2 + kbl) * 64);
            #pragma unroll
            for (int nt = 0; nt < 4; nt++)
                #pragma unroll
                for (int mt = 0; mt < 2; mt++) {
                    MMA_TF32(accL[mt][nt], af[0][mt], bf[0][nt]);
                    MMA_TF32(ac4s[mt][nt], af[0][mt], bf[2][nt]);
                    MMA_TF32(ac4e[mt][nt], af[1][mt], bf[2][nt]);
                    MMA_TF32(accL[mt][nt], af[1][mt], bf[1][nt]);
                }
        }
        __syncthreads();
    }

    // epilogue
    const float* b4p  = span ? bh4 : bp4;
    const float* c12p = g_c12[span];
    float* outp = out + (size_t)span * MTOT * HID;

    #pragma unroll
    for (int mt = 0; mt < 2; mt++) {
        const int r0 = m0 + wm * 32 + mt * 16 + (lane >> 2);
        #pragma unroll
        for (int nt = 0; nt < 4; nt++) {
            const int o = n0 + wn * 32 + nt * 8 + (lane & 3) * 2;
            const float c0 = c12p[o],   c1 = c12p[o + 1];
            const float d0 = b4p[o],    d1 = b4p[o + 1];
            float v0 = accL[mt][nt][0] + c0 + (ac4s[mt][nt][0] + d0) * (ac4e[mt][nt][0] + d0);
            float v1 = accL[mt][nt][1] + c1 + (ac4s[mt][nt][1] + d1) * (ac4e[mt][nt][1] + d1);
            *(float2*)&outp[(size_t)r0 * HID + o] = make_float2(tanhf(v0), tanhf(v1));
            float v2 = accL[mt][nt][2] + c0 + (ac4s[mt][nt][2] + d0) * (ac4e[mt][nt][2] + d0);
            float v3 = accL[mt][nt][3] + c1 + (ac4s[mt][nt][3] + d1) * (ac4e[mt][nt][3] + d1);
            *(float2*)&outp[(size_t)(r0 + 8) * HID + o] = make_float2(tanhf(v2), tanhf(v3));
        }
    }
}

// ---------------- launch ----------------
extern "C" void kernel_launch(void* const* d_in, const int* in_sizes, int n_in,
                              void* d_out, int out_size) {
    const float* x    = (const float*)d_in[0];
    const void*  prem = d_in[1];
    const void*  hypo = d_in[2];
    const float* Wp1 = (const float*)d_in[3];
    const float* bp1 = (const float*)d_in[4];
    const float* Wp2 = (const float*)d_in[5];
    const float* bp2 = (const float*)d_in[6];
    const float* Wp3 = (const float*)d_in[7];
    const float* Wp4 = (const float*)d_in[9];
    const float* bp4 = (const float*)d_in[10];
    const float* Wh1 = (const float*)d_in[11];
    const float* bh1 = (const float*)d_in[12];
    const float* Wh2 = (const float*)d_in[13];
    const float* bh2 = (const float*)d_in[14];
    const float* Wh3 = (const float*)d_in[15];
    const float* Wh4 = (const float*)d_in[17];
    const float* bh4 = (const float*)d_in[18];
    float* out = (float*)d_out;

    detect_idx_kernel<<<1, 32>>>((const unsigned int*)prem);
    bias_kernel<<<1, HID>>>(bp1, bp2, bh1, bh2);

    weights_permute<<<dim3(NBT, 2), 256>>>(Wp1, Wp2, Wp3, Wp4, Wh1, Wh2, Wh3, Wh4);
    gather_permute<<<dim3(MBT, 2, 2), 256>>>(x, prem, hypo);

    cudaFuncSetAttribute(gemm_kernel, cudaFuncAttributeMaxDynamicSharedMemorySize, SMEM_BYTES);
    gemm_kernel<<<dim3(HID / TN, MTOT / TM, 2), 256, SMEM_BYTES>>>(bp4, bh4, out);
}

// round 10
// speedup vs baseline: 8.0227x; 1.1263x over previous
#include <cuda_runtime.h>
#include <math.h>
#include <stdint.h>

// Problem dims: B=16, S=1024, H=1024, K=256
#define BATCH 16
#define SEQ   1024
#define HID   1024
#define KIDX  256
#define MTOT  (BATCH * KIDX)      // 4096 rows per span
#define MBT   (MTOT / 16)          // 256 m-blocks (16 rows each)
#define NBT   (HID / 8)            // 128 n-blocks (8 cols each)
#define KB8T  (HID / 8)            // 128 k8-blocks

// GEMM tiling: CTA 64x128, 8 warps (2x4), warp tile 32x32, k-chunk 32 (4 kb8)
#define TM    64
#define TN    128
#define NCH   (HID / 32)           // 32 chunks
#define STAGES 3
#define STAGE_FL 16384             // floats per stage: A 4096 + B 12288 (64KB)
#define SMEM_BYTES (STAGES * STAGE_FL * 4)   // 192KB

// ---------------- device scratch (fragment-ordered, tf32-rounded) -------
// A: [span][which][mb][kb8][lane] float4 = {A[r][c],A[r+8][c],A[r][c+4],A[r+8][c+4]},
//    r=lane>>2, c=lane&3 (within 16x8 block).
__device__ float g_Af[2][2][(size_t)MBT * KB8T * 32 * 4];
// B: [span][op][nb][kb8][lane] float2 = {W[n][k],W[n][k+4]}, n=lane>>2,k=lane&3. op: W13,W23,W4
__device__ float g_Wf[2][3][(size_t)NBT * KB8T * 32 * 2];
__device__ float g_c12[2][HID];
__device__ int   g_is64[2];

// ---------------- helpers ----------------
__device__ __forceinline__ uint32_t smem_u32(const void* p) {
    uint32_t a;
    asm("{ .reg .u64 t; cvta.to.shared.u64 t, %1; cvt.u32.u64 %0, t; }" : "=r"(a) : "l"(p));
    return a;
}
__device__ __forceinline__ float tf32r(float f) {
    uint32_t u;
    asm("cvt.rna.tf32.f32 %0, %1;" : "=r"(u) : "f"(f));
    return __uint_as_float(u);
}

#define MMA_TF32(c, a, b_) \
    asm volatile("mma.sync.aligned.m16n8k8.row.col.f32.tf32.tf32.f32 " \
        "{%0,%1,%2,%3}, {%4,%5,%6,%7}, {%8,%9}, {%0,%1,%2,%3};" \
        : "+f"((c)[0]), "+f"((c)[1]), "+f"((c)[2]), "+f"((c)[3]) \
        : "r"(__float_as_uint((a).x)), "r"(__float_as_uint((a).y)), \
          "r"(__float_as_uint((a).z)), "r"(__float_as_uint((a).w)), \
          "r"(__float_as_uint((b_).x)), "r"(__float_as_uint((b_).y)))

// ---------------- prep kernels ----------------
__global__ void detect_idx_kernel(const unsigned int* __restrict__ prem_raw) {
    if (threadIdx.x == 0) {
        int all_zero = 1;
        #pragma unroll
        for (int i = 0; i < 32; i++)
            if (prem_raw[2 * i + 1] != 0u) all_zero = 0;
        g_is64[0] = all_zero;
        g_is64[1] = 0;
    }
}

// grid (MBT, 2 which, 2 span), 256 threads: gather 16 rows -> fragment layout
__global__ void gather_permute(const float* __restrict__ x,
                               const void* __restrict__ prem,
                               const void* __restrict__ hypo) {
    const int mb    = blockIdx.x;
    const int which = blockIdx.y;
    const int span  = blockIdx.z;
    const void* idx_raw = span ? hypo : prem;

    __shared__ int sidx[16];
    if (threadIdx.x < 16) {
        const int m = mb * 16 + threadIdx.x;
        const int b = m >> 8;
        const int k = m & (KIDX - 1);
        const long off = ((long)b * 2 + which) * KIDX + k;
        int s;
        if (g_is64[span]) s = (int)((const long long*)idx_raw)[off];
        else              s = ((const int*)idx_raw)[off];
        sidx[threadIdx.x] = b * SEQ + s;
    }
    __syncthreads();

    const int lane = threadIdx.x & 31;
    const int w    = threadIdx.x >> 5;
    const int r    = lane >> 2;
    const int c    = lane & 3;
    const float* r0p = x + (size_t)sidx[r] * HID;
    const float* r8p = x + (size_t)sidx[r + 8] * HID;
    float4* dst = (float4*)g_Af[span][which] + (size_t)mb * KB8T * 32;

    #pragma unroll
    for (int i = 0; i < 16; i++) {
        const int kb8 = w + 8 * i;
        const int k = kb8 * 8 + c;
        float4 v = make_float4(tf32r(__ldg(r0p + k)),     tf32r(__ldg(r8p + k)),
                               tf32r(__ldg(r0p + k + 4)), tf32r(__ldg(r8p + k + 4)));
        dst[(size_t)kb8 * 32 + lane] = v;
    }
}

// grid (NBT, 2 span), 256 threads: fold weights -> fragment layout (+bias fold)
__global__ void weights_permute(const float* __restrict__ Wp1, const float* __restrict__ Wp2,
                                const float* __restrict__ Wp3, const float* __restrict__ Wp4,
                                const float* __restrict__ Wh1, const float* __restrict__ Wh2,
                                const float* __restrict__ Wh3, const float* __restrict__ Wh4,
                                const float* __restrict__ bp1, const float* __restrict__ bp2,
                                const float* __restrict__ bh1, const float* __restrict__ bh2) {
    const int nb   = blockIdx.x;
    const int span = blockIdx.y;
    const float* W1 = span ? Wh1 : Wp1;
    const float* W2 = span ? Wh2 : Wp2;
    const float* W3 = span ? Wh3 : Wp3;
    const float* W4 = span ? Wh4 : Wp4;

    if (nb < 4) {   // fold biases: 4 blocks x 256 threads = 1024
        const int i = nb * 256 + threadIdx.x;
        g_c12[span][i] = span ? (bh1[i] + bh2[i]) : (bp1[i] + bp2[i]);
    }

    const int lane = threadIdx.x & 31;
    const int w    = threadIdx.x >> 5;
    const int n    = nb * 8 + (lane >> 2);
    const int c    = lane & 3;
    float2* d13 = (float2*)g_Wf[span][0] + (size_t)nb * KB8T * 32;
    float2* d23 = (float2*)g_Wf[span][1] + (size_t)nb * KB8T * 32;
    float2* d4  = (float2*)g_Wf[span][2] + (size_t)nb * KB8T * 32;

    #pragma unroll
    for (int i = 0; i < 16; i++) {
        const int kb8 = w + 8 * i;
        const size_t ka = (size_t)n * HID + kb8 * 8 + c;
        const float w1a = __ldg(W1 + ka), w1b = __ldg(W1 + ka + 4);
        const float w2a = __ldg(W2 + ka), w2b = __ldg(W2 + ka + 4);
        const float w3a = __ldg(W3 + ka), w3b = __ldg(W3 + ka + 4);
        const float w4a = __ldg(W4 + ka), w4b = __ldg(W4 + ka + 4);
        const size_t o = (size_t)kb8 * 32 + lane;
        d13[o] = make_float2(tf32r(w1a + w3a), tf32r(w1b + w3b));
        d23[o] = make_float2(tf32r(w2a - w3a), tf32r(w2b - w3b));
        d4[o]  = make_float2(tf32r(w4a), tf32r(w4b));
    }
}

// ---------------- main fused GEMM (tf32 mma.sync, fragment smem) ---------
// out = tanh(accL + c12 + (ac4s+b4)*(ac4e+b4))
__global__ __launch_bounds__(256, 1)
void gemm_kernel(const float* __restrict__ bp4, const float* __restrict__ bh4,
                 float* __restrict__ out) {
    extern __shared__ float smf[];
    const int tid  = threadIdx.x;
    const int wid  = tid >> 5;
    const int lane = tid & 31;
    const int span = blockIdx.z;
    const int n0   = blockIdx.x * TN;
    const int m0   = blockIdx.y * TM;
    const int mb0  = m0 >> 4;
    const int nb0  = n0 >> 3;
    const int wm   = wid >> 2;         // 0..1
    const int wn   = wid & 3;          // 0..3

    // loader slots: 4096 x 16B per chunk / 256 threads = 16 slots.
    // smem stage layout (floats): A [0, 4096) = [o][mbl][j][lane]f4,
    //                             B [4096, 16384) = [w][nbl][j][q]f4
    const float4* gb[16];
    int so[16], adv[16];
    #pragma unroll
    for (int s = 0; s < 16; s++) {
        const int v = s * 256 + tid;
        if (v < 1024) {
            const int l   = v & 31;
            const int j   = (v >> 5) & 3;
            const int mbl = (v >> 7) & 3;
            const int o   = v >> 9;
            gb[s]  = (const float4*)g_Af[span][o] +
                     (size_t)(mb0 + mbl) * (KB8T * 32) + j * 32 + l;
            so[s]  = v * 4;
            adv[s] = 4 * 32;           // 4 kb8 per chunk
        } else {
            const int u  = v - 1024;
            const int q  = u & 15;
            const int j  = (u >> 4) & 3;
            const int nb = (u >> 6) & 15;
            const int w  = u >> 10;
            gb[s]  = (const float4*)g_Wf[span][w] +
                     (size_t)(nb0 + nb) * (KB8T * 16) + j * 16 + q;
            so[s]  = 4096 + u * 4;
            adv[s] = 4 * 16;
        }
    }
    const uint32_t sbu = smem_u32(smf);

#define LOAD_CHUNK(ch, st) do {                                                  \
        _Pragma("unroll")                                                        \
        for (int _s = 0; _s < 16; _s++) {                                        \
            uint32_t _d = sbu + (uint32_t)(((st) * STAGE_FL + so[_s]) * 4);      \
            asm volatile("cp.async.cg.shared.global [%0], [%1], 16;"             \
                         :: "r"(_d), "l"(gb[_s] + (size_t)(ch) * adv[_s])        \
                         : "memory");                                            \
        }                                                                        \
    } while (0)

    float accL[2][4][4] = {}, ac4s[2][4][4] = {}, ac4e[2][4][4] = {};

    // prologue: 2 chunks in flight (stage = ch % 3)
    LOAD_CHUNK(0, 0);
    asm volatile("cp.async.commit_group;" ::: "memory");
    LOAD_CHUNK(1, 1);
    asm volatile("cp.async.commit_group;" ::: "memory");

    const int aOff = lane * 4;         // + ((o*4 + wm*2+mt)*4 + kbl)*128
    const int bOff = 4096 + lane * 2;  // + ((w*16 + wn*4+nt)*4 + kbl)*64

    int st = 0;                        // stage of chunk ch (= ch % 3)
    for (int ch = 0; ch < NCH; ch++) {
        asm volatile("cp.async.wait_group 1;" ::: "memory");
        __syncthreads();
        // issue next load into stage (ch+2) % 3; empty commit keeps group
        // accounting uniform so wait_group 1 always completes chunk ch.
        if (ch + 2 < NCH) {
            int stn = st + 2; if (stn >= STAGES) stn -= STAGES;
            LOAD_CHUNK(ch + 2, stn);
        }
        asm volatile("cp.async.commit_group;" ::: "memory");

        const int S0 = st * STAGE_FL;
        st = (st + 1 == STAGES) ? 0 : st + 1;

        #pragma unroll
        for (int kbl = 0; kbl < 4; kbl++) {
            float4 af[2][2];
            #pragma unroll
            for (int o = 0; o < 2; o++)
                #pragma unroll
                for (int mt = 0; mt < 2; mt++)
                    af[o][mt] = *(const float4*)(smf + S0 + aOff +
                                ((o * 4 + wm * 2 + mt) * 4 + kbl) * 128);
            float2 bf[3][4];
            #pragma unroll
            for (int w = 0; w < 3; w++)
                #pragma unroll
                for (int nt = 0; nt < 4; nt++)
                    bf[w][nt] = *(const float2*)(smf + S0 + bOff +
                                ((w * 16 + wn * 4 + nt) * 4 + kbl) * 64);
            // long same-accumulator reuse distance: 6 MMAs between accL hits
            #pragma unroll
            for (int nt = 0; nt < 4; nt++) {
                MMA_TF32(accL[0][nt], af[0][0], bf[0][nt]);
                MMA_TF32(accL[1][nt], af[0][1], bf[0][nt]);
                MMA_TF32(ac4s[0][nt], af[0][0], bf[2][nt]);
                MMA_TF32(ac4s[1][nt], af[0][1], bf[2][nt]);
                MMA_TF32(ac4e[0][nt], af[1][0], bf[2][nt]);
                MMA_TF32(ac4e[1][nt], af[1][1], bf[2][nt]);
                MMA_TF32(accL[0][nt], af[1][0], bf[1][nt]);
                MMA_TF32(accL[1][nt], af[1][1], bf[1][nt]);
            }
        }
        // no trailing __syncthreads: stage st(ch) is only overwritten by
        // LOAD_CHUNK(ch+3), issued after the barrier in iteration ch+1,
        // which orders all warps' iteration-ch reads before those writes.
    }

    // epilogue
    const float* b4p  = span ? bh4 : bp4;
    const float* c12p = g_c12[span];
    float* outp = out + (size_t)span * MTOT * HID;

    #pragma unroll
    for (int mt = 0; mt < 2; mt++) {
        const int r0 = m0 + wm * 32 + mt * 16 + (lane >> 2);
        #pragma unroll
        for (int nt = 0; nt < 4; nt++) {
            const int o = n0 + wn * 32 + nt * 8 + (lane & 3) * 2;
            const float c0 = c12p[o],   c1 = c12p[o + 1];
            const float d0 = b4p[o],    d1 = b4p[o + 1];
            float v0 = accL[mt][nt][0] + c0 + (ac4s[mt][nt][0] + d0) * (ac4e[mt][nt][0] + d0);
            float v1 = accL[mt][nt][1] + c1 + (ac4s[mt][nt][1] + d1) * (ac4e[mt][nt][1] + d1);
            *(float2*)&outp[(size_t)r0 * HID + o] = make_float2(tanhf(v0), tanhf(v1));
            float v2 = accL[mt][nt][2] + c0 + (ac4s[mt][nt][2] + d0) * (ac4e[mt][nt][2] + d0);
            float v3 = accL[mt][nt][3] + c1 + (ac4s[mt][nt][3] + d1) * (ac4e[mt][nt][3] + d1);
            *(float2*)&outp[(size_t)(r0 + 8) * HID + o] = make_float2(tanhf(v2), tanhf(v3));
        }
    }
}

// ---------------- launch ----------------
extern "C" void kernel_launch(void* const* d_in, const int* in_sizes, int n_in,
                              void* d_out, int out_size) {
    const float* x    = (const float*)d_in[0];
    const void*  prem = d_in[1];
    const void*  hypo = d_in[2];
    const float* Wp1 = (const float*)d_in[3];
    const float* bp1 = (const float*)d_in[4];
    const float* Wp2 = (const float*)d_in[5];
    const float* bp2 = (const float*)d_in[6];
    const float* Wp3 = (const float*)d_in[7];
    const float* Wp4 = (const float*)d_in[9];
    const float* bp4 = (const float*)d_in[10];
    const float* Wh1 = (const float*)d_in[11];
    const float* bh1 = (const float*)d_in[12];
    const float* Wh2 = (const float*)d_in[13];
    const float* bh2 = (const float*)d_in[14];
    const float* Wh3 = (const float*)d_in[15];
    const float* Wh4 = (const float*)d_in[17];
    const float* bh4 = (const float*)d_in[18];
    float* out = (float*)d_out;

    detect_idx_kernel<<<1, 32>>>((const unsigned int*)prem);

    weights_permute<<<dim3(NBT, 2), 256>>>(Wp1, Wp2, Wp3, Wp4, Wh1, Wh2, Wh3, Wh4,
                                           bp1, bp2, bh1, bh2);
    gather_permute<<<dim3(MBT, 2, 2), 256>>>(x, prem, hypo);

    cudaFuncSetAttribute(gemm_kernel, cudaFuncAttributeMaxDynamicSharedMemorySize, SMEM_BYTES);
    gemm_kernel<<<dim3(HID / TN, MTOT / TM, 2), 256, SMEM_BYTES>>>(bp4, bh4, out);
}

// round 12
// speedup vs baseline: 14.3768x; 1.7920x over previous
#include <cuda_runtime.h>
#include <cuda_fp16.h>
#include <math.h>
#include <stdint.h>

// Problem dims: B=16, S=1024, H=1024, K=256
#define BATCH 16
#define SEQ   1024
#define HID   1024
#define KIDX  256
#define MTOT  (BATCH * KIDX)      // 4096 rows per span
#define MBT   (MTOT / 16)          // 256 m-blocks (16 rows)
#define NBT   (HID / 8)            // 128 n-blocks (8 cols)
#define KB16T (HID / 16)           // 64 k16-blocks

// GEMM tiling: CTA 64x128, 8 warps (2x4), warp tile 32x32, k-chunk 64 (4 kb16)
#define TM    64
#define TN    128
#define NCH   (HID / 64)           // 16 chunks
#define STAGES 3
#define STAGE_U32 16384            // u32 per stage: A 4096 + B 12288 (64KB)
#define SMEM_BYTES (STAGES * STAGE_U32 * 4)   // 192KB

// ---------------- device scratch (fp16 fragment-ordered) ----------------
// A: [span][which][mb][kb16][lane] uint4 = {a0,a1,a2,a3} half2 regs of m16k16
//    frag: r=lane>>2, c2=(lane&3)*2; a0=(r,c2:c2+1) a1=(r+8,..) a2=(r,c2+8..) a3=(r+8,c2+8..)
__device__ uint4 g_Af[2][2][(size_t)MBT * KB16T * 32];
// B: [span][op][nb][kb16][lane] uint2 = {b0,b1} half2 regs of n8k16
//    frag: n=lane>>2, c2=(lane&3)*2; b0=(n, k c2:c2+1) b1=(n, k c2+8:c2+9). op: W13,W23,W4
__device__ uint2 g_Wf[2][3][(size_t)NBT * KB16T * 32];
__device__ float g_c12[2][HID];
__device__ int   g_is64[2];

// ---------------- helpers ----------------
__device__ __forceinline__ uint32_t smem_u32(const void* p) {
    uint32_t a;
    asm("{ .reg .u64 t; cvta.to.shared.u64 t, %1; cvt.u32.u64 %0, t; }" : "=r"(a) : "l"(p));
    return a;
}
__device__ __forceinline__ uint32_t pack2(float lo, float hi) {
    __half2 h = __floats2half2_rn(lo, hi);   // lo -> low 16 bits (k even first)
    return *(uint32_t*)&h;
}

#define MMA_F16(c, a, b_) \
    asm volatile("mma.sync.aligned.m16n8k16.row.col.f32.f16.f16.f32 " \
        "{%0,%1,%2,%3}, {%4,%5,%6,%7}, {%8,%9}, {%0,%1,%2,%3};" \
        : "+f"((c)[0]), "+f"((c)[1]), "+f"((c)[2]), "+f"((c)[3]) \
        : "r"((a).x), "r"((a).y), "r"((a).z), "r"((a).w), \
          "r"((b_).x), "r"((b_).y))

// ---------------- prep kernels ----------------
__global__ void detect_idx_kernel(const unsigned int* __restrict__ prem_raw) {
    if (threadIdx.x == 0) {
        int all_zero = 1;
        #pragma unroll
        for (int i = 0; i < 32; i++)
            if (prem_raw[2 * i + 1] != 0u) all_zero = 0;
        g_is64[0] = all_zero;
        g_is64[1] = 0;
    }
}

// grid (MBT, 2 which, 2 span), 256 threads: gather 16 rows -> fp16 fragments
__global__ void gather_permute(const float* __restrict__ x,
                               const void* __restrict__ prem,
                               const void* __restrict__ hypo) {
    const int mb    = blockIdx.x;
    const int which = blockIdx.y;
    const int span  = blockIdx.z;
    const void* idx_raw = span ? hypo : prem;

    __shared__ int sidx[16];
    if (threadIdx.x < 16) {
        const int m = mb * 16 + threadIdx.x;
        const int b = m >> 8;
        const int k = m & (KIDX - 1);
        const long off = ((long)b * 2 + which) * KIDX + k;
        int s;
        if (g_is64[span]) s = (int)((const long long*)idx_raw)[off];
        else              s = ((const int*)idx_raw)[off];
        sidx[threadIdx.x] = b * SEQ + s;
    }
    __syncthreads();

    const int lane = threadIdx.x & 31;
    const int w    = threadIdx.x >> 5;
    const int r    = lane >> 2;
    const int c2   = (lane & 3) * 2;
    const float* r0p = x + (size_t)sidx[r] * HID;
    const float* r8p = x + (size_t)sidx[r + 8] * HID;
    uint4* dst = g_Af[span][which] + (size_t)mb * KB16T * 32;

    #pragma unroll
    for (int i = 0; i < 8; i++) {
        const int kb16 = w + 8 * i;
        const int k = kb16 * 16 + c2;
        float2 v0 = __ldg((const float2*)(r0p + k));
        float2 v1 = __ldg((const float2*)(r8p + k));
        float2 v2 = __ldg((const float2*)(r0p + k + 8));
        float2 v3 = __ldg((const float2*)(r8p + k + 8));
        uint4 o;
        o.x = pack2(v0.x, v0.y);
        o.y = pack2(v1.x, v1.y);
        o.z = pack2(v2.x, v2.y);
        o.w = pack2(v3.x, v3.y);
        dst[(size_t)kb16 * 32 + lane] = o;
    }
}

// grid (NBT, 2 span), 256 threads: fold weights -> fp16 fragments (+bias fold)
__global__ void weights_permute(const float* __restrict__ Wp1, const float* __restrict__ Wp2,
                                const float* __restrict__ Wp3, const float* __restrict__ Wp4,
                                const float* __restrict__ Wh1, const float* __restrict__ Wh2,
                                const float* __restrict__ Wh3, const float* __restrict__ Wh4,
                                const float* __restrict__ bp1, const float* __restrict__ bp2,
                                const float* __restrict__ bh1, const float* __restrict__ bh2) {
    const int nb   = blockIdx.x;
    const int span = blockIdx.y;
    const float* W1 = span ? Wh1 : Wp1;
    const float* W2 = span ? Wh2 : Wp2;
    const float* W3 = span ? Wh3 : Wp3;
    const float* W4 = span ? Wh4 : Wp4;

    if (nb < 4) {
        const int i = nb * 256 + threadIdx.x;
        g_c12[span][i] = span ? (bh1[i] + bh2[i]) : (bp1[i] + bp2[i]);
    }

    const int lane = threadIdx.x & 31;
    const int w    = threadIdx.x >> 5;
    const int n    = nb * 8 + (lane >> 2);
    const int c2   = (lane & 3) * 2;
    uint2* d13 = g_Wf[span][0] + (size_t)nb * KB16T * 32;
    uint2* d23 = g_Wf[span][1] + (size_t)nb * KB16T * 32;
    uint2* d4  = g_Wf[span][2] + (size_t)nb * KB16T * 32;

    #pragma unroll
    for (int i = 0; i < 8; i++) {
        const int kb16 = w + 8 * i;
        const size_t ka = (size_t)n * HID + kb16 * 16 + c2;
        float2 w1a = __ldg((const float2*)(W1 + ka));
        float2 w1b = __ldg((const float2*)(W1 + ka + 8));
        float2 w2a = __ldg((const float2*)(W2 + ka));
        float2 w2b = __ldg((const float2*)(W2 + ka + 8));
        float2 w3a = __ldg((const float2*)(W3 + ka));
        float2 w3b = __ldg((const float2*)(W3 + ka + 8));
        float2 w4a = __ldg((const float2*)(W4 + ka));
        float2 w4b = __ldg((const float2*)(W4 + ka + 8));
        const size_t o = (size_t)kb16 * 32 + lane;
        d13[o] = make_uint2(pack2(w1a.x + w3a.x, w1a.y + w3a.y),
                            pack2(w1b.x + w3b.x, w1b.y + w3b.y));
        d23[o] = make_uint2(pack2(w2a.x - w3a.x, w2a.y - w3a.y),
                            pack2(w2b.x - w3b.x, w2b.y - w3b.y));
        d4[o]  = make_uint2(pack2(w4a.x, w4a.y), pack2(w4b.x, w4b.y));
    }
}

// ---------------- main fused GEMM (fp16 mma.sync, fragment smem) ---------
// out = tanh(accL + c12 + (ac4s+b4)*(ac4e+b4))
__global__ __launch_bounds__(256, 1)
void gemm_kernel(const float* __restrict__ bp4, const float* __restrict__ bh4,
                 float* __restrict__ out) {
    extern __shared__ uint32_t smu[];
    const int tid  = threadIdx.x;
    const int wid  = tid >> 5;
    const int lane = tid & 31;
    const int span = blockIdx.z;
    const int n0   = blockIdx.x * TN;
    const int m0   = blockIdx.y * TM;
    const int mb0  = m0 >> 4;
    const int nb0  = n0 >> 3;
    const int wm   = wid >> 2;         // 0..1
    const int wn   = wid & 3;          // 0..3

    // loader slots: 4096 x 16B per chunk / 256 threads = 16 slots.
    // smem stage layout (u32): A [0, 4096) = [o][mbl][j][lane]u4,
    //                          B [4096, 16384) = [w][nbl][j][q]u4 (q pairs lanes)
    const uint4* gb[16];
    int so[16], adv[16];
    #pragma unroll
    for (int s = 0; s < 16; s++) {
        const int v = s * 256 + tid;
        if (v < 1024) {
            const int l   = v & 31;
            const int j   = (v >> 5) & 3;
            const int mbl = (v >> 7) & 3;
            const int o   = v >> 9;
            gb[s]  = g_Af[span][o] + (size_t)(mb0 + mbl) * (KB16T * 32) + j * 32 + l;
            so[s]  = v * 4;
            adv[s] = 4 * 32;           // 4 kb16 per chunk
        } else {
            const int u  = v - 1024;   // 0..3071
            const int q  = u & 15;
            const int j  = (u >> 4) & 3;
            const int nb = (u >> 6) & 15;
            const int w  = u >> 10;
            gb[s]  = (const uint4*)g_Wf[span][w] +
                     (size_t)(nb0 + nb) * (KB16T * 16) + j * 16 + q;
            so[s]  = 4096 + u * 4;
            adv[s] = 4 * 16;
        }
    }
    const uint32_t sbu = smem_u32(smu);

#define LOAD_CHUNK(ch, st) do {                                                  \
        _Pragma("unroll")                                                        \
        for (int _s = 0; _s < 16; _s++) {                                        \
            uint32_t _d = sbu + (uint32_t)(((st) * STAGE_U32 + so[_s]) * 4);     \
            asm volatile("cp.async.cg.shared.global [%0], [%1], 16;"             \
                         :: "r"(_d), "l"(gb[_s] + (size_t)(ch) * adv[_s])        \
                         : "memory");                                            \
        }                                                                        \
    } while (0)

    float accL[2][4][4] = {}, ac4s[2][4][4] = {}, ac4e[2][4][4] = {};

    // prologue: 2 chunks in flight (stage = ch % 3)
    LOAD_CHUNK(0, 0);
    asm volatile("cp.async.commit_group;" ::: "memory");
    LOAD_CHUNK(1, 1);
    asm volatile("cp.async.commit_group;" ::: "memory");

    const int aOff = lane * 4;         // + ((o*4 + wm*2+mt)*4 + kbl)*128
    const int bOff = 4096 + lane * 2;  // + ((w*16 + wn*4+nt)*4 + kbl)*64

    int st = 0;                        // stage of chunk ch (= ch % 3)
    for (int ch = 0; ch < NCH; ch++) {
        asm volatile("cp.async.wait_group 1;" ::: "memory");
        __syncthreads();
        // issue next load into stage (ch+2)%3; empty commit keeps group
        // accounting uniform so wait_group 1 always completes chunk ch.
        if (ch + 2 < NCH) {
            int stn = st + 2; if (stn >= STAGES) stn -= STAGES;
            LOAD_CHUNK(ch + 2, stn);
        }
        asm volatile("cp.async.commit_group;" ::: "memory");

        const int S0 = st * STAGE_U32;
        st = (st + 1 == STAGES) ? 0 : st + 1;

        #pragma unroll
        for (int kbl = 0; kbl < 4; kbl++) {
            uint4 af[2][2];
            #pragma unroll
            for (int o = 0; o < 2; o++)
                #pragma unroll
                for (int mt = 0; mt < 2; mt++)
                    af[o][mt] = *(const uint4*)(smu + S0 + aOff +
                                ((o * 4 + wm * 2 + mt) * 4 + kbl) * 128);
            uint2 bf[3][4];
            #pragma unroll
            for (int w = 0; w < 3; w++)
                #pragma unroll
                for (int nt = 0; nt < 4; nt++)
                    bf[w][nt] = *(const uint2*)(smu + S0 + bOff +
                                ((w * 16 + wn * 4 + nt) * 4 + kbl) * 64);
            // long same-accumulator reuse distance: 6 MMAs between accL hits
            #pragma unroll
            for (int nt = 0; nt < 4; nt++) {
                MMA_F16(accL[0][nt], af[0][0], bf[0][nt]);
                MMA_F16(accL[1][nt], af[0][1], bf[0][nt]);
                MMA_F16(ac4s[0][nt], af[0][0], bf[2][nt]);
                MMA_F16(ac4s[1][nt], af[0][1], bf[2][nt]);
                MMA_F16(ac4e[0][nt], af[1][0], bf[2][nt]);
                MMA_F16(ac4e[1][nt], af[1][1], bf[2][nt]);
                MMA_F16(accL[0][nt], af[1][0], bf[1][nt]);
                MMA_F16(accL[1][nt], af[1][1], bf[1][nt]);
            }
        }
        // no trailing __syncthreads: stage st(ch) is only overwritten by
        // LOAD_CHUNK(ch+3), issued after the barrier in iteration ch+1.
    }

    // epilogue (accumulator layout identical to tf32 m16n8k8 case)
    const float* b4p  = span ? bh4 : bp4;
    const float* c12p = g_c12[span];
    float* outp = out + (size_t)span * MTOT * HID;

    #pragma unroll
    for (int mt = 0; mt < 2; mt++) {
        const int r0 = m0 + wm * 32 + mt * 16 + (lane >> 2);
        #pragma unroll
        for (int nt = 0; nt < 4; nt++) {
            const int o = n0 + wn * 32 + nt * 8 + (lane & 3) * 2;
            const float c0 = c12p[o],   c1 = c12p[o + 1];
            const float d0 = b4p[o],    d1 = b4p[o + 1];
            float v0 = accL[mt][nt][0] + c0 + (ac4s[mt][nt][0] + d0) * (ac4e[mt][nt][0] + d0);
            float v1 = accL[mt][nt][1] + c1 + (ac4s[mt][nt][1] + d1) * (ac4e[mt][nt][1] + d1);
            *(float2*)&outp[(size_t)r0 * HID + o] = make_float2(tanhf(v0), tanhf(v1));
            float v2 = accL[mt][nt][2] + c0 + (ac4s[mt][nt][2] + d0) * (ac4e[mt][nt][2] + d0);
            float v3 = accL[mt][nt][3] + c1 + (ac4s[mt][nt][3] + d1) * (ac4e[mt][nt][3] + d1);
            *(float2*)&outp[(size_t)(r0 + 8) * HID + o] = make_float2(tanhf(v2), tanhf(v3));
        }
    }
}

// ---------------- launch ----------------
extern "C" void kernel_launch(void* const* d_in, const int* in_sizes, int n_in,
                              void* d_out, int out_size) {
    const float* x    = (const float*)d_in[0];
    const void*  prem = d_in[1];
    const void*  hypo = d_in[2];
    const float* Wp1 = (const float*)d_in[3];
    const float* bp1 = (const float*)d_in[4];
    const float* Wp2 = (const float*)d_in[5];
    const float* bp2 = (const float*)d_in[6];
    const float* Wp3 = (const float*)d_in[7];
    const float* Wp4 = (const float*)d_in[9];
    const float* bp4 = (const float*)d_in[10];
    const float* Wh1 = (const float*)d_in[11];
    const float* bh1 = (const float*)d_in[12];
    const float* Wh2 = (const float*)d_in[13];
    const float* bh2 = (const float*)d_in[14];
    const float* Wh3 = (const float*)d_in[15];
    const float* Wh4 = (const float*)d_in[17];
    const float* bh4 = (const float*)d_in[18];
    float* out = (float*)d_out;

    detect_idx_kernel<<<1, 32>>>((const unsigned int*)prem);

    weights_permute<<<dim3(NBT, 2), 256>>>(Wp1, Wp2, Wp3, Wp4, Wh1, Wh2, Wh3, Wh4,
                                           bp1, bp2, bh1, bh2);
    gather_permute<<<dim3(MBT, 2, 2), 256>>>(x, prem, hypo);

    cudaFuncSetAttribute(gemm_kernel, cudaFuncAttributeMaxDynamicSharedMemorySize, SMEM_BYTES);
    gemm_kernel<<<dim3(HID / TN, MTOT / TM, 2), 256, SMEM_BYTES>>>(bp4, bh4, out);
}